// round 1
// baseline (speedup 1.0000x reference)
#include <cuda_runtime.h>
#include <cstdint>

// DiffGatedTopK: x [N=16384, D=4096] fp32.
// k = int(D*0.15) = 614. out = x * topk_mask * (sigmoid(top1-top2)*3 + 1)

#define DCOLS 4096
#define KSEL  614
#define NTHREADS 256
#define GAIN_C 3.0f

// float -> order-preserving unsigned key
__device__ __forceinline__ unsigned f2k(unsigned u) {
    return u ^ ((unsigned)(((int)u) >> 31) | 0x80000000u);
}
// inverse
__device__ __forceinline__ float k2f(unsigned k) {
    unsigned b = (k & 0x80000000u) ? (k ^ 0x80000000u) : ~k;
    return __uint_as_float(b);
}

__device__ __forceinline__ void top2_upd(unsigned &m1, unsigned &m2, unsigned v) {
    if (v > m1) { m2 = m1; m1 = v; }
    else if (v > m2) { m2 = v; }
}

__device__ __forceinline__ int warp_incl_scan(int v, int lane) {
    #pragma unroll
    for (int o = 1; o < 32; o <<= 1) {
        int n = __shfl_up_sync(0xFFFFFFFFu, v, o);
        if (lane >= o) v += n;
    }
    return v;
}

__global__ void __launch_bounds__(NTHREADS, 8)
diff_gated_topk_kernel(const float* __restrict__ x, float* __restrict__ out) {
    const int row  = blockIdx.x;
    const int tid  = threadIdx.x;
    const int lane = tid & 31;
    const int wid  = tid >> 5;

    const float4* __restrict__ xr =
        reinterpret_cast<const float4*>(x + (size_t)row * DCOLS);
    float4* __restrict__ orow =
        reinterpret_cast<float4*>(out + (size_t)row * DCOLS);

    __shared__ unsigned hist[256];
    __shared__ unsigned s_ctrl[3];   // [0]=prefix  [1]=remaining  [2]=eq_count
    __shared__ unsigned s_m[16];     // per-warp (m1,m2)
    __shared__ float    s_gain;
    __shared__ int      s_warp[8];   // block-scan scratch

    // ---- load 16 values/thread into registers, coalesced float4 ----
    uint4 kq[4];
    unsigned m1 = 0u, m2 = 0u;
    #pragma unroll
    for (int i = 0; i < 4; i++) {
        float4 v = xr[tid + i * NTHREADS];
        uint4 kk;
        kk.x = f2k(__float_as_uint(v.x));
        kk.y = f2k(__float_as_uint(v.y));
        kk.z = f2k(__float_as_uint(v.z));
        kk.w = f2k(__float_as_uint(v.w));
        top2_upd(m1, m2, kk.x); top2_upd(m1, m2, kk.y);
        top2_upd(m1, m2, kk.z); top2_upd(m1, m2, kk.w);
        kq[i] = kk;
    }

    // ---- block top-2 (multiset) reduction in key space ----
    #pragma unroll
    for (int off = 16; off; off >>= 1) {
        unsigned o1 = __shfl_down_sync(0xFFFFFFFFu, m1, off);
        unsigned o2 = __shfl_down_sync(0xFFFFFFFFu, m2, off);
        unsigned n1 = max(m1, o1);
        unsigned n2 = max(min(m1, o1), max(m2, o2));
        m1 = n1; m2 = n2;
    }
    if (lane == 0) { s_m[2 * wid] = m1; s_m[2 * wid + 1] = m2; }
    if (tid == 0) { s_ctrl[0] = 0u; s_ctrl[1] = (unsigned)KSEL; }
    __syncthreads();
    if (tid == 0) {
        unsigned a1 = s_m[0], a2 = s_m[1];
        #pragma unroll
        for (int w = 1; w < 8; w++) {
            unsigned b1 = s_m[2 * w], b2 = s_m[2 * w + 1];
            unsigned n1 = max(a1, b1);
            a2 = max(min(a1, b1), max(a2, b2));
            a1 = n1;
        }
        float v1 = k2f(a1), v2 = k2f(a2);
        float d  = v1 - v2;                 // >= 0
        s_gain = GAIN_C / (1.0f + expf(-d)) + 1.0f;
    }

    // ---- 4-pass 8-bit radix select for exact k-th largest key ----
    #pragma unroll
    for (int pass = 0; pass < 4; pass++) {
        const int shift = 24 - 8 * pass;
        hist[tid] = 0u;
        __syncthreads();
        const unsigned pref  = s_ctrl[0];
        const unsigned pmask = pass ? (0xFFFFFFFFu << (shift + 8)) : 0u;

        #pragma unroll
        for (int i = 0; i < 4; i++) {
            unsigned kk[4] = { kq[i].x, kq[i].y, kq[i].z, kq[i].w };
            #pragma unroll
            for (int j = 0; j < 4; j++) {
                unsigned key = kk[j];
                bool act = ((key & pmask) == pref);
                unsigned bin = (key >> shift) & 0xFFu;
                // warp-aggregated histogram: inactive lanes get unique dummies
                unsigned tag = act ? bin : (0x100u + (unsigned)lane);
                unsigned grp = __match_any_sync(0xFFFFFFFFu, tag);
                int leader = __ffs(grp) - 1;
                if (act && lane == leader)
                    atomicAdd(&hist[bin], (unsigned)__popc(grp));
            }
        }
        __syncthreads();
        if (tid == 0) {
            unsigned rem = s_ctrl[1];
            unsigned cum = 0;
            int b = 255;
            for (; b >= 0; b--) {
                unsigned c = hist[b];
                if (cum + c >= rem) break;
                cum += c;
            }
            s_ctrl[0] = pref | ((unsigned)b << shift);
            s_ctrl[1] = rem - cum;          // needed from the == bucket
            if (pass == 3) s_ctrl[2] = hist[b];  // eq_count
        }
        __syncthreads();
    }

    const unsigned T      = s_ctrl[0];
    const unsigned needed = s_ctrl[1];
    const unsigned eqc    = s_ctrl[2];
    const float    gain   = s_gain;
    const bool use_rank   = (eqc != needed);   // rare: duplicated threshold value

    // ---- rare path: rank equal-to-threshold elements in exact column order ----
    // column(c) = i*1024 + tid*4 + j  -> order over (i, tid, j)
    int base[4] = {0, 0, 0, 0};
    if (use_rank) {
        int chunkbase = 0;
        #pragma unroll
        for (int i = 0; i < 4; i++) {
            unsigned kk[4] = { kq[i].x, kq[i].y, kq[i].z, kq[i].w };
            int c = (kk[0] == T) + (kk[1] == T) + (kk[2] == T) + (kk[3] == T);
            int incl = warp_incl_scan(c, lane);
            if (lane == 31) s_warp[wid] = incl;
            __syncthreads();
            if (wid == 0) {
                int w = (lane < 8) ? s_warp[lane] : 0;
                int wi = warp_incl_scan(w, lane);
                if (lane < 8) s_warp[lane] = wi;
            }
            __syncthreads();
            int offset = wid ? s_warp[wid - 1] : 0;
            base[i] = chunkbase + offset + incl - c;
            chunkbase += s_warp[7];
            __syncthreads();   // protect s_warp reuse
        }
    }

    // ---- write pass: reconstruct x from keys (no 2nd global read) ----
    #pragma unroll
    for (int i = 0; i < 4; i++) {
        unsigned kk[4] = { kq[i].x, kq[i].y, kq[i].z, kq[i].w };
        int r = base[i];
        float o[4];
        #pragma unroll
        for (int j = 0; j < 4; j++) {
            unsigned key = kk[j];
            bool inc;
            if (key > T) inc = true;
            else if (key == T) {
                if (!use_rank) inc = true;
                else { inc = (r < (int)needed); r++; }
            } else inc = false;
            o[j] = inc ? (k2f(key) * gain) : 0.0f;
        }
        float4 ov = make_float4(o[0], o[1], o[2], o[3]);
        orow[tid + i * NTHREADS] = ov;
    }
}

extern "C" void kernel_launch(void* const* d_in, const int* in_sizes, int n_in,
                              void* d_out, int out_size) {
    const float* x = (const float*)d_in[0];
    float* out = (float*)d_out;
    int nrows = in_sizes[0] / DCOLS;
    diff_gated_topk_kernel<<<nrows, NTHREADS>>>(x, out);
}